// round 10
// baseline (speedup 1.0000x reference)
#include <cuda_runtime.h>
#include <cstdint>
#include <math.h>

// Problem constants
#define Bb   8
#define Tt   2048
#define Dd   1024
#define Hh   8
#define Cc   64
#define DVv  128
#define Mm   (Bb*Tt)
#define PSTR  768
#define CH   16
#define QVS  1536          // merged q|v row stride

// ---------------- scratch -------------------------------------------------
__device__ float g_xn  [(size_t)Mm*Dd];
__device__ float g_wall[(size_t)PSTR*Dd];
__device__ float g_hw  [(size_t)QVS*Cc];      // rows 0-511: Qc concat; 512-1535: Vc concat
__device__ float g_proj[(size_t)Mm*PSTR];     // qlat|kn|vlat|alpha(sigmoided)
__device__ float g_qv  [(size_t)Mm*QVS];      // [m][ q(512) | v(1024) ]
__device__ float g_o   [(size_t)Mm*Dd];

// ---------------- 0. dummy (keeps ncu capture slot on the proj GEMM) ------
__global__ void dummy_k() {}

// ---------------- 1. LayerNorm -------------------------------------------
__global__ __launch_bounds__(256)
void ln_kernel(const float* __restrict__ x, const float* __restrict__ gamma,
               const float* __restrict__ beta)
{
    int row = blockIdx.x;
    int tid = threadIdx.x;
    const float4* xr = (const float4*)(x + (size_t)row*Dd);
    float4 v = xr[tid];
    float s  = v.x + v.y + v.z + v.w;
    float s2 = v.x*v.x + v.y*v.y + v.z*v.z + v.w*v.w;
    #pragma unroll
    for (int o = 16; o > 0; o >>= 1) {
        s  += __shfl_xor_sync(0xffffffffu, s,  o);
        s2 += __shfl_xor_sync(0xffffffffu, s2, o);
    }
    __shared__ float r1[8], r2[8];
    int w = tid >> 5, l = tid & 31;
    if (l == 0) { r1[w] = s; r2[w] = s2; }
    __syncthreads();
    s = 0.f; s2 = 0.f;
    #pragma unroll
    for (int i = 0; i < 8; i++) { s += r1[i]; s2 += r2[i]; }
    float mu  = s * (1.f/Dd);
    float var = s2 * (1.f/Dd) - mu*mu;
    float inv = rsqrtf(var + 1e-5f);
    float4 g  = ((const float4*)gamma)[tid];
    float4 be = ((const float4*)beta)[tid];
    float4 o;
    o.x = (v.x - mu)*inv*g.x + be.x;
    o.y = (v.y - mu)*inv*g.y + be.y;
    o.z = (v.z - mu)*inv*g.z + be.z;
    o.w = (v.w - mu)*inv*g.w + be.w;
    ((float4*)(g_xn + (size_t)row*Dd))[tid] = o;
}

// ---------------- 2. weight prep ------------------------------------------
#define WALL_ELEMS (PSTR*Dd)
#define HW_ELEMS   (QVS*Cc)
__global__ void prep_weights(const float* __restrict__ Wq, const float* __restrict__ Wk,
                             const float* __restrict__ Wv, const float* __restrict__ Wa,
                             const float* __restrict__ Qc, const float* __restrict__ Vc)
{
    int i = blockIdx.x * blockDim.x + threadIdx.x;
    if (i < WALL_ELEMS) {
        int row = i >> 10, col = i & 1023;
        float val;
        if      (row <  64) val = Wq[(size_t)row       *1024 + col];
        else if (row < 128) val = Wk[(size_t)(row- 64) *1024 + col];
        else if (row < 192) val = Wv[(size_t)(row-128) *1024 + col];
        else if (row < 704) val = Wa[(size_t)(row-192) *1024 + col];
        else                val = 0.f;
        g_wall[i] = val;
    } else if (i < WALL_ELEMS + HW_ELEMS) {
        int j = i - WALL_ELEMS;
        int n = j >> 6, c = j & 63;
        if (n < 512) {         // q rows: n = h*64+e
            int h = n >> 6, e = n & 63;
            g_hw[j] = Qc[(size_t)h*Cc*Cc + (size_t)c*Cc + e];
        } else {               // v rows: n-512 = h*128+d
            int nn = n - 512;
            int h = nn >> 7, d = nn & 127;
            g_hw[j] = Vc[(size_t)h*Cc*DVv + (size_t)c*DVv + d];
        }
    }
}

// ---------------- 3. TF32 GEMM, 32x64 warp tile, 256 thr ------------------
// Y[M,N] = A[M,K] @ W[N,K]^T. Block tile 128x128, 8 warps in 4(M)x2(N) grid.
// mode 0: plain; 1: += resid; 2: proj epilogue (knorm cols 64-127, sigmoid 192-703)
// mode 3: merged head GEMM (blocks with col0>=512 shift A by +128 to v_lat)
__device__ __forceinline__ uint32_t f2tf32(float f) {
    uint32_t u;
    asm volatile("cvt.rna.tf32.f32 %0, %1;" : "=r"(u) : "f"(f));
    return u;
}
__device__ __forceinline__ void mma_tf32(float c[4], const uint32_t a[4], const uint32_t b[2]) {
    asm volatile(
        "mma.sync.aligned.m16n8k8.row.col.f32.tf32.tf32.f32 "
        "{%0,%1,%2,%3}, {%4,%5,%6,%7}, {%8,%9}, {%0,%1,%2,%3};\n"
        : "+f"(c[0]), "+f"(c[1]), "+f"(c[2]), "+f"(c[3])
        : "r"(a[0]), "r"(a[1]), "r"(a[2]), "r"(a[3]), "r"(b[0]), "r"(b[1]));
}

__global__ __launch_bounds__(256, 2)
void gemm_tf32(int K, int lda, int ldy, int mode,
               const float* __restrict__ A,
               const float* __restrict__ W,
               float* __restrict__ Y,
               const float* __restrict__ resid,
               const float* __restrict__ bias)
{
    __shared__ uint32_t As[2][128*20];
    __shared__ uint32_t Bs[2][128*20];

    int tid  = threadIdx.x;
    int lane = tid & 31, warp = tid >> 5;
    int wm = warp & 3, wn = warp >> 2;       // 4x2 warp grid, tile 32x64
    int g  = lane >> 2, tig = lane & 3;
    int row0 = blockIdx.y * 128;
    int col0 = blockIdx.x * 128;
    if (mode == 3 && col0 >= 512) A += 128;  // v_lat slice

    // loader: 256 threads; each stages one 8-k slab of one A row + one B row
    int lrow = tid >> 1;            // 0..127
    int kb   = (tid & 1) * 8;       // slab offset
    const float* Ap = A + (size_t)(row0 + lrow) * lda + kb;
    const float* Bp = W + (size_t)(col0 + lrow) * K + kb;

    float acc[2][8][4];
    #pragma unroll
    for (int i = 0; i < 2; i++)
        #pragma unroll
        for (int j = 0; j < 8; j++)
            #pragma unroll
            for (int e = 0; e < 4; e++) acc[i][j][e] = 0.f;

    // preload k0 = 0
    {
        float4 a0 = *(const float4*)(Ap);
        float4 a1 = *(const float4*)(Ap + 4);
        float4 b0 = *(const float4*)(Bp);
        float4 b1 = *(const float4*)(Bp + 4);
        *(uint4*)&As[0][lrow*20 + kb]     = make_uint4(f2tf32(a0.x), f2tf32(a0.y), f2tf32(a0.z), f2tf32(a0.w));
        *(uint4*)&As[0][lrow*20 + kb + 4] = make_uint4(f2tf32(a1.x), f2tf32(a1.y), f2tf32(a1.z), f2tf32(a1.w));
        *(uint4*)&Bs[0][lrow*20 + kb]     = make_uint4(f2tf32(b0.x), f2tf32(b0.y), f2tf32(b0.z), f2tf32(b0.w));
        *(uint4*)&Bs[0][lrow*20 + kb + 4] = make_uint4(f2tf32(b1.x), f2tf32(b1.y), f2tf32(b1.z), f2tf32(b1.w));
    }
    __syncthreads();

    int buf = 0;
    for (int k0 = 0; k0 < K; k0 += 16) {
        float4 pa0, pa1, pb0, pb1;
        bool more = (k0 + 16) < K;
        if (more) {
            const float* Ak = Ap + k0 + 16;
            const float* Bk = Bp + k0 + 16;
            pa0 = *(const float4*)(Ak);
            pa1 = *(const float4*)(Ak + 4);
            pb0 = *(const float4*)(Bk);
            pb1 = *(const float4*)(Bk + 4);
        }

        const uint32_t* Ab  = As[buf];
        const uint32_t* Bb_ = Bs[buf];
        #pragma unroll
        for (int ks = 0; ks < 16; ks += 8) {
            uint32_t af[2][4], bf[8][2];
            #pragma unroll
            for (int i = 0; i < 2; i++) {
                int base = (wm*32 + i*16 + g)*20 + ks + tig;
                af[i][0] = Ab[base];
                af[i][1] = Ab[base + 8*20];
                af[i][2] = Ab[base + 4];
                af[i][3] = Ab[base + 8*20 + 4];
            }
            #pragma unroll
            for (int j = 0; j < 8; j++) {
                int base = (wn*64 + j*8 + g)*20 + ks + tig;
                bf[j][0] = Bb_[base];
                bf[j][1] = Bb_[base + 4];
            }
            #pragma unroll
            for (int i = 0; i < 2; i++)
                #pragma unroll
                for (int j = 0; j < 8; j++)
                    mma_tf32(acc[i][j], af[i], bf[j]);
        }

        if (more) {
            int nb = buf ^ 1;
            *(uint4*)&As[nb][lrow*20 + kb]     = make_uint4(f2tf32(pa0.x), f2tf32(pa0.y), f2tf32(pa0.z), f2tf32(pa0.w));
            *(uint4*)&As[nb][lrow*20 + kb + 4] = make_uint4(f2tf32(pa1.x), f2tf32(pa1.y), f2tf32(pa1.z), f2tf32(pa1.w));
            *(uint4*)&Bs[nb][lrow*20 + kb]     = make_uint4(f2tf32(pb0.x), f2tf32(pb0.y), f2tf32(pb0.z), f2tf32(pb0.w));
            *(uint4*)&Bs[nb][lrow*20 + kb + 4] = make_uint4(f2tf32(pb1.x), f2tf32(pb1.y), f2tf32(pb1.z), f2tf32(pb1.w));
            __syncthreads();
            buf = nb;
        }
    }

    bool knorm_warp = (mode == 2) && (col0 + wn*64 == 64);
    #pragma unroll
    for (int i = 0; i < 2; i++) {
        #pragma unroll
        for (int half = 0; half < 2; half++) {
            int m = row0 + wm*32 + i*16 + g + half*8;
            float scale = 1.f;
            if (knorm_warp) {
                float s = 0.f;
                #pragma unroll
                for (int j = 0; j < 8; j++) {
                    float e0 = acc[i][j][half*2], e1 = acc[i][j][half*2+1];
                    s = fmaf(e0, e0, s); s = fmaf(e1, e1, s);
                }
                s += __shfl_xor_sync(0xffffffffu, s, 1);
                s += __shfl_xor_sync(0xffffffffu, s, 2);
                scale = 1.f / fmaxf(sqrtf(s), 1e-12f);
            }
            #pragma unroll
            for (int j = 0; j < 8; j++) {
                int n0 = col0 + wn*64 + j*8 + tig*2;
                float2 val = make_float2(acc[i][j][half*2], acc[i][j][half*2+1]);
                if (mode == 1) {
                    const float2 r = *(const float2*)(resid + (size_t)m*ldy + n0);
                    val.x += r.x; val.y += r.y;
                } else if (mode == 2) {
                    if (knorm_warp) {
                        val.x *= scale; val.y *= scale;
                    } else if (n0 >= 192 && n0 < 704) {
                        float2 bb = *(const float2*)(bias + n0 - 192);
                        val.x = 1.f / (1.f + expf(-(val.x + bb.x)));
                        val.y = 1.f / (1.f + expf(-(val.y + bb.y)));
                    }
                }
                *(float2*)(Y + (size_t)m*ldy + n0) = val;
            }
        }
    }
}

// ---------------- 4. recurrent scan (8c x 2v tiles, chunked) ---------------
// Block = (b,h,vhalf). 256 threads: vg = tid>>3 (32 v-pairs), cg = tid&7 (8 c's).
__global__ __launch_bounds__(256)
void scan_kernel()
{
    int blk   = blockIdx.x;
    int bh    = blk >> 1;
    int vhalf = blk & 1;
    int b = bh >> 3, h = bh & 7;
    int tid = threadIdx.x;
    int vg  = tid >> 3;      // 0..31
    int cg  = tid & 7;       // 0..7
    const float* qp = g_qv + (size_t)(b*Tt)*QVS + h*64;
    const float* vp = g_qv + (size_t)(b*Tt)*QVS + 512 + h*128 + vhalf*64;
    const float* pp = g_proj + (size_t)b * Tt * PSTR;
    float* op = g_o + (size_t)b * Tt * Dd + h*DVv + vhalf*64 + vg*2;

    // chunk loader: flat float4 index f = i*256 + tid; q4=f&15, s=(f>>4)&3, r=f>>6
    const float* lsrc[4];
    size_t ladv[4];
    int ldst[4];
    #pragma unroll
    for (int i = 0; i < 4; i++) {
        int f = i * 256 + tid;
        int lq4 = f & 15, ls = (f >> 4) & 3, lr = f >> 6;
        switch (ls) {
            case 0:  lsrc[i] = pp + (size_t)lr*PSTR + 192 + h*64 + lq4*4; ladv[i] = (size_t)CH*PSTR; break;
            case 1:  lsrc[i] = pp + (size_t)lr*PSTR + 64 + lq4*4;         ladv[i] = (size_t)CH*PSTR; break;
            case 2:  lsrc[i] = qp + (size_t)lr*QVS + lq4*4;               ladv[i] = (size_t)CH*QVS;  break;
            default: lsrc[i] = vp + (size_t)lr*QVS + lq4*4;               ladv[i] = (size_t)CH*QVS;  break;
        }
        ldst[i] = (lr*4 + ls)*64 + lq4*4;
    }

    __shared__ __align__(16) float sh[2][CH*256];
    float S0[8], S1[8];
    #pragma unroll
    for (int i = 0; i < 8; i++) { S0[i] = 0.f; S1[i] = 0.f; }

    #pragma unroll
    for (int i = 0; i < 4; i++)
        *(float4*)&sh[0][ldst[i]] = *(const float4*)lsrc[i];
    __syncthreads();

    int buf = 0;
    for (int c = 0; c < Tt/CH; c++) {
        float4 pf[4];
        bool more = (c + 1) < (Tt/CH);
        if (more) {
            #pragma unroll
            for (int i = 0; i < 4; i++)
                pf[i] = *(const float4*)(lsrc[i] + (size_t)(c+1)*ladv[i]);
        }
        const float* cb = sh[buf];
        #pragma unroll 4
        for (int r = 0; r < CH; r++) {
            const float* base = cb + r*256;
            float4 a0 = *(const float4*)(base +       cg*8);
            float4 a1 = *(const float4*)(base +       cg*8 + 4);
            float4 k0 = *(const float4*)(base +  64 + cg*8);
            float4 k1 = *(const float4*)(base +  64 + cg*8 + 4);
            float4 q0 = *(const float4*)(base + 128 + cg*8);
            float4 q1 = *(const float4*)(base + 128 + cg*8 + 4);
            float2 vt = *(const float2*)(base + 192 + vg*2);
            float acc0 = 0.f, acc1 = 0.f;

            S0[0] = fmaf(a0.x, S0[0], k0.x*vt.x); acc0 = fmaf(q0.x, S0[0], acc0);
            S1[0] = fmaf(a0.x, S1[0], k0.x*vt.y); acc1 = fmaf(q0.x, S1[0], acc1);
            S0[1] = fmaf(a0.y, S0[1], k0.y*vt.x); acc0 = fmaf(q0.y, S0[1], acc0);
            S1[1] = fmaf(a0.y, S1[1], k0.y*vt.y); acc1 = fmaf(q0.y, S1[1], acc1);
            S0[2] = fmaf(a0.z, S0[2], k0.z*vt.x); acc0 = fmaf(q0.z, S0[2], acc0);
            S1[2] = fmaf(a0.z, S1[2], k0.z*vt.y); acc1 = fmaf(q0.z, S1[2], acc1);
            S0[3] = fmaf(a0.w, S0[3], k0.w*vt.x); acc0 = fmaf(q0.w, S0[3], acc0);
            S1[3] = fmaf(a0.w, S1[3], k0.w*vt.y); acc1 = fmaf(q0.w, S1[3], acc1);
            S0[4] = fmaf(a1.x, S0[4], k1.x*vt.x); acc0 = fmaf(q1.x, S0[4], acc0);
            S1[4] = fmaf(a1.x, S1[4], k1.x*vt.y); acc1 = fmaf(q1.x, S1[4], acc1);
            S0[5] = fmaf(a1.y, S0[5], k1.y*vt.x); acc0 = fmaf(q1.y, S0[5], acc0);
            S1[5] = fmaf(a1.y, S1[5], k1.y*vt.y); acc1 = fmaf(q1.y, S1[5], acc1);
            S0[6] = fmaf(a1.z, S0[6], k1.z*vt.x); acc0 = fmaf(q1.z, S0[6], acc0);
            S1[6] = fmaf(a1.z, S1[6], k1.z*vt.y); acc1 = fmaf(q1.z, S1[6], acc1);
            S0[7] = fmaf(a1.w, S0[7], k1.w*vt.x); acc0 = fmaf(q1.w, S0[7], acc0);
            S1[7] = fmaf(a1.w, S1[7], k1.w*vt.y); acc1 = fmaf(q1.w, S1[7], acc1);

            acc0 += __shfl_xor_sync(0xffffffffu, acc0, 1);
            acc1 += __shfl_xor_sync(0xffffffffu, acc1, 1);
            acc0 += __shfl_xor_sync(0xffffffffu, acc0, 2);
            acc1 += __shfl_xor_sync(0xffffffffu, acc1, 2);
            acc0 += __shfl_xor_sync(0xffffffffu, acc0, 4);
            acc1 += __shfl_xor_sync(0xffffffffu, acc1, 4);
            if (cg == 0)
                *(float2*)(op + (size_t)(c*CH + r) * Dd) = make_float2(acc0, acc1);
        }
        if (more) {
            int nb = buf ^ 1;
            #pragma unroll
            for (int i = 0; i < 4; i++)
                *(float4*)&sh[nb][ldst[i]] = pf[i];
            __syncthreads();
            buf = nb;
        }
    }
}

// ---------------- launch ---------------------------------------------------
extern "C" void kernel_launch(void* const* d_in, const int* in_sizes, int n_in,
                              void* d_out, int out_size)
{
    const float* x     = (const float*)d_in[0];
    const float* Wq    = (const float*)d_in[1];
    const float* Wk    = (const float*)d_in[2];
    const float* Wv    = (const float*)d_in[3];
    const float* Qc    = (const float*)d_in[4];
    const float* Vc    = (const float*)d_in[5];
    const float* Wa_w  = (const float*)d_in[6];
    const float* Wa_b  = (const float*)d_in[7];
    const float* Wo    = (const float*)d_in[8];
    const float* gamma = (const float*)d_in[9];
    const float* beta  = (const float*)d_in[10];
    float* out = (float*)d_out;

    float *xn, *wall, *hw, *proj, *qv, *o;
    cudaGetSymbolAddress((void**)&xn,   g_xn);
    cudaGetSymbolAddress((void**)&wall, g_wall);
    cudaGetSymbolAddress((void**)&hw,   g_hw);
    cudaGetSymbolAddress((void**)&proj, g_proj);
    cudaGetSymbolAddress((void**)&qv,   g_qv);
    cudaGetSymbolAddress((void**)&o,    g_o);

    int prep_total = WALL_ELEMS + HW_ELEMS;

    // 0: layernorm
    ln_kernel<<<Mm, 256>>>(x, gamma, beta);
    // 1: weight prep
    prep_weights<<<(prep_total + 255)/256, 256>>>(Wq, Wk, Wv, Wa_w, Qc, Vc);
    // 2: dummy (keeps ncu capture slot 3 on the projection GEMM)
    dummy_k<<<1, 32>>>();
    // 3: projection GEMM + fused epi (knorm + sigmoid)
    gemm_tf32<<<dim3(PSTR/128, Mm/128), 256>>>(Dd, Dd, PSTR, 2, xn, wall, proj, nullptr, Wa_b);
    // 4: merged head GEMM: qv[16384,1536] = [q_lat|v_lat] @ hw^T (K=64)
    gemm_tf32<<<dim3(QVS/128, Mm/128), 256>>>(Cc, PSTR, QVS, 3, proj, hw, qv, nullptr, nullptr);
    // 5: recurrent scan
    scan_kernel<<<128, 256>>>();
    // 6: output GEMM + residual
    gemm_tf32<<<dim3(Dd/128, Mm/128), 256>>>(Dd, Dd, Dd, 1, o, Wo, out, x, nullptr);
}

// round 12
// speedup vs baseline: 1.1286x; 1.1286x over previous
#include <cuda_runtime.h>
#include <cstdint>
#include <math.h>

// Problem constants
#define Bb   8
#define Tt   2048
#define Dd   1024
#define Hh   8
#define Cc   64
#define DVv  128
#define Mm   (Bb*Tt)
#define PSTR  768
#define CH   16
#define QVS  1536

// ---------------- scratch -------------------------------------------------
__device__ float g_xn  [(size_t)Mm*Dd];       // tf32-rounded layernorm out
__device__ float g_wall[(size_t)PSTR*Dd];     // tf32-rounded proj weights
__device__ float g_hw  [(size_t)QVS*Cc];      // tf32-rounded head weights
__device__ float g_wo  [(size_t)Dd*Dd];       // tf32-rounded output weights
__device__ float g_proj[(size_t)Mm*PSTR];     // qlat|kn|vlat|alpha (q/v tf32-rounded)
__device__ float g_qv  [(size_t)Mm*QVS];
__device__ float g_o   [(size_t)Mm*Dd];       // tf32-rounded scan out

__device__ __forceinline__ uint32_t f2tf32(float f) {
    uint32_t u;
    asm volatile("cvt.rna.tf32.f32 %0, %1;" : "=r"(u) : "f"(f));
    return u;
}
__device__ __forceinline__ float tf32r(float f) { return __uint_as_float(f2tf32(f)); }

__device__ __forceinline__ uint32_t smem_u32(const void* p) {
    uint32_t a;
    asm("{ .reg .u64 t; cvta.to.shared.u64 t, %1; cvt.u32.u64 %0, t; }" : "=r"(a) : "l"(p));
    return a;
}
__device__ __forceinline__ void cp16(uint32_t dst, const void* src) {
    asm volatile("cp.async.cg.shared.global [%0], [%1], 16;" :: "r"(dst), "l"(src));
}
#define CP_COMMIT() asm volatile("cp.async.commit_group;" ::: "memory")
#define CP_WAIT(n)  asm volatile("cp.async.wait_group %0;" :: "n"(n) : "memory")

// ---------------- 0. dummy (keeps ncu slot 3 on proj GEMM) ----------------
__global__ void dummy_k() {}

// ---------------- 1. LayerNorm (tf32-rounded output) ----------------------
__global__ __launch_bounds__(256)
void ln_kernel(const float* __restrict__ x, const float* __restrict__ gamma,
               const float* __restrict__ beta)
{
    int row = blockIdx.x;
    int tid = threadIdx.x;
    const float4* xr = (const float4*)(x + (size_t)row*Dd);
    float4 v = xr[tid];
    float s  = v.x + v.y + v.z + v.w;
    float s2 = v.x*v.x + v.y*v.y + v.z*v.z + v.w*v.w;
    #pragma unroll
    for (int o = 16; o > 0; o >>= 1) {
        s  += __shfl_xor_sync(0xffffffffu, s,  o);
        s2 += __shfl_xor_sync(0xffffffffu, s2, o);
    }
    __shared__ float r1[8], r2[8];
    int w = tid >> 5, l = tid & 31;
    if (l == 0) { r1[w] = s; r2[w] = s2; }
    __syncthreads();
    s = 0.f; s2 = 0.f;
    #pragma unroll
    for (int i = 0; i < 8; i++) { s += r1[i]; s2 += r2[i]; }
    float mu  = s * (1.f/Dd);
    float var = s2 * (1.f/Dd) - mu*mu;
    float inv = rsqrtf(var + 1e-5f);
    float4 g  = ((const float4*)gamma)[tid];
    float4 be = ((const float4*)beta)[tid];
    float4 o;
    o.x = tf32r((v.x - mu)*inv*g.x + be.x);
    o.y = tf32r((v.y - mu)*inv*g.y + be.y);
    o.z = tf32r((v.z - mu)*inv*g.z + be.z);
    o.w = tf32r((v.w - mu)*inv*g.w + be.w);
    ((float4*)(g_xn + (size_t)row*Dd))[tid] = o;
}

// ---------------- 2. weight prep (tf32-rounded) ---------------------------
#define WALL_ELEMS (PSTR*Dd)
#define HW_ELEMS   (QVS*Cc)
#define WO_ELEMS   (Dd*Dd)
__global__ void prep_weights(const float* __restrict__ Wq, const float* __restrict__ Wk,
                             const float* __restrict__ Wv, const float* __restrict__ Wa,
                             const float* __restrict__ Qc, const float* __restrict__ Vc,
                             const float* __restrict__ Wo)
{
    int i = blockIdx.x * blockDim.x + threadIdx.x;
    if (i < WALL_ELEMS) {
        int row = i >> 10, col = i & 1023;
        float val;
        if      (row <  64) val = Wq[(size_t)row       *1024 + col];
        else if (row < 128) val = Wk[(size_t)(row- 64) *1024 + col];
        else if (row < 192) val = Wv[(size_t)(row-128) *1024 + col];
        else if (row < 704) val = Wa[(size_t)(row-192) *1024 + col];
        else                val = 0.f;
        g_wall[i] = tf32r(val);
    } else if (i < WALL_ELEMS + HW_ELEMS) {
        int j = i - WALL_ELEMS;
        int n = j >> 6, c = j & 63;
        float val;
        if (n < 512) { int h = n >> 6, e = n & 63;  val = Qc[(size_t)h*Cc*Cc + (size_t)c*Cc + e]; }
        else { int nn = n - 512; int h = nn >> 7, d = nn & 127; val = Vc[(size_t)h*Cc*DVv + (size_t)c*DVv + d]; }
        g_hw[j] = tf32r(val);
    } else if (i < WALL_ELEMS + HW_ELEMS + WO_ELEMS) {
        int j = i - WALL_ELEMS - HW_ELEMS;
        g_wo[j] = tf32r(Wo[j]);
    }
}

// ---------------- 3. TF32 GEMM, 64x64 warp tile, cp.async loaders ---------
// Y[M,N] = A[M,K] @ W[N,K]^T. 128 threads, 2x2 warps. Inputs pre-rounded tf32.
// mode 0 plain | 1 +resid | 2 proj epilogue | 3 head (col0>=512 -> A+=128)
__device__ __forceinline__ void mma_tf32(float c[4], const uint32_t a[4], const uint32_t b[2]) {
    asm volatile(
        "mma.sync.aligned.m16n8k8.row.col.f32.tf32.tf32.f32 "
        "{%0,%1,%2,%3}, {%4,%5,%6,%7}, {%8,%9}, {%0,%1,%2,%3};\n"
        : "+f"(c[0]), "+f"(c[1]), "+f"(c[2]), "+f"(c[3])
        : "r"(a[0]), "r"(a[1]), "r"(a[2]), "r"(a[3]), "r"(b[0]), "r"(b[1]));
}

__global__ __launch_bounds__(128, 3)
void gemm_tf32(int K, int lda, int ldy, int mode,
               const float* __restrict__ A,
               const float* __restrict__ W,
               float* __restrict__ Y,
               const float* __restrict__ resid,
               const float* __restrict__ bias)
{
    __shared__ uint32_t As[2][128*20];
    __shared__ uint32_t Bs[2][128*20];

    int tid  = threadIdx.x;
    int lane = tid & 31, warp = tid >> 5;
    int wm = warp & 1, wn = warp >> 1;       // 2x2 warp grid, 64x64 tiles
    int g  = lane >> 2, tig = lane & 3;
    int row0 = blockIdx.y * 128;
    int col0 = blockIdx.x * 128;
    if (mode == 3 && col0 >= 512) A += 128;

    // cp.async loader: 512 16B-chunks per tile; 4 per thread per tile
    uint32_t asb = smem_u32(As), bsb = smem_u32(Bs);
    const float* Abase = A + (size_t)row0 * lda;
    const float* Bbase = W + (size_t)col0 * K;

    float acc[4][8][4];
    #pragma unroll
    for (int i = 0; i < 4; i++)
        #pragma unroll
        for (int j = 0; j < 8; j++)
            #pragma unroll
            for (int e = 0; e < 4; e++) acc[i][j][e] = 0.f;

    // prologue: chunk 0 into buf 0
    #pragma unroll
    for (int i = 0; i < 4; i++) {
        int s = tid + i*128;
        int row = s >> 2, q = s & 3;
        uint32_t soff = (uint32_t)(row*20 + q*4) * 4;
        cp16(asb + soff, Abase + (size_t)row*lda + q*4);
        cp16(bsb + soff, Bbase + (size_t)row*K   + q*4);
    }
    CP_COMMIT();

    int NC = K >> 4;
    for (int c = 0; c < NC; c++) {
        int buf = c & 1;
        if (c + 1 < NC) {
            int nb = buf ^ 1;
            int k0 = (c + 1) << 4;
            uint32_t ab = asb + (uint32_t)nb * (128*20*4);
            uint32_t bb = bsb + (uint32_t)nb * (128*20*4);
            #pragma unroll
            for (int i = 0; i < 4; i++) {
                int s = tid + i*128;
                int row = s >> 2, q = s & 3;
                uint32_t soff = (uint32_t)(row*20 + q*4) * 4;
                cp16(ab + soff, Abase + (size_t)row*lda + k0 + q*4);
                cp16(bb + soff, Bbase + (size_t)row*K   + k0 + q*4);
            }
            CP_COMMIT();
            CP_WAIT(1);
        } else {
            CP_WAIT(0);
        }
        __syncthreads();

        const uint32_t* Ab  = As[buf];
        const uint32_t* Bb_ = Bs[buf];
        #pragma unroll
        for (int ks = 0; ks < 16; ks += 8) {
            uint32_t af[4][4], bf[8][2];
            #pragma unroll
            for (int i = 0; i < 4; i++) {
                int base = (wm*64 + i*16 + g)*20 + ks + tig;
                af[i][0] = Ab[base];
                af[i][1] = Ab[base + 8*20];
                af[i][2] = Ab[base + 4];
                af[i][3] = Ab[base + 8*20 + 4];
            }
            #pragma unroll
            for (int j = 0; j < 8; j++) {
                int base = (wn*64 + j*8 + g)*20 + ks + tig;
                bf[j][0] = Bb_[base];
                bf[j][1] = Bb_[base + 4];
            }
            #pragma unroll
            for (int i = 0; i < 4; i++)
                #pragma unroll
                for (int j = 0; j < 8; j++)
                    mma_tf32(acc[i][j], af[i], bf[j]);
        }
        __syncthreads();   // protect buf before it is refilled at c+2
    }

    bool knorm_warp = (mode == 2) && (col0 + wn*64 == 64);
    #pragma unroll
    for (int i = 0; i < 4; i++) {
        #pragma unroll
        for (int half = 0; half < 2; half++) {
            int m = row0 + wm*64 + i*16 + g + half*8;
            float scale = 1.f;
            if (knorm_warp) {
                float s = 0.f;
                #pragma unroll
                for (int j = 0; j < 8; j++) {
                    float e0 = acc[i][j][half*2], e1 = acc[i][j][half*2+1];
                    s = fmaf(e0, e0, s); s = fmaf(e1, e1, s);
                }
                s += __shfl_xor_sync(0xffffffffu, s, 1);
                s += __shfl_xor_sync(0xffffffffu, s, 2);
                scale = 1.f / fmaxf(sqrtf(s), 1e-12f);
            }
            #pragma unroll
            for (int j = 0; j < 8; j++) {
                int n0 = col0 + wn*64 + j*8 + tig*2;
                float2 val = make_float2(acc[i][j][half*2], acc[i][j][half*2+1]);
                if (mode == 1) {
                    const float2 r = *(const float2*)(resid + (size_t)m*ldy + n0);
                    val.x += r.x; val.y += r.y;
                } else if (mode == 2) {
                    if (knorm_warp) {
                        val.x *= scale; val.y *= scale;
                    } else if (n0 < 192) {             // q_lat / v_lat: feed head GEMM
                        val.x = tf32r(val.x); val.y = tf32r(val.y);
                    } else if (n0 < 704) {             // alpha
                        float2 bb = *(const float2*)(bias + n0 - 192);
                        val.x = 1.f / (1.f + expf(-(val.x + bb.x)));
                        val.y = 1.f / (1.f + expf(-(val.y + bb.y)));
                    }
                } else if (mode == 3) {
                    val.x = tf32r(val.x); val.y = tf32r(val.y);   // unused rounding-neutral? no:
                    // qv feeds only the scan (fp32 math), rounding harmless but unnecessary;
                    // keep values exact instead:
                    val = make_float2(acc[i][j][half*2], acc[i][j][half*2+1]);
                }
                *(float2*)(Y + (size_t)m*ldy + n0) = val;
            }
        }
    }
}

// ---------------- 4. recurrent scan (8c x 2v tiles, chunked) ---------------
__global__ __launch_bounds__(256)
void scan_kernel()
{
    int blk   = blockIdx.x;
    int bh    = blk >> 1;
    int vhalf = blk & 1;
    int b = bh >> 3, h = bh & 7;
    int tid = threadIdx.x;
    int vg  = tid >> 3;
    int cg  = tid & 7;
    const float* qp = g_qv + (size_t)(b*Tt)*QVS + h*64;
    const float* vp = g_qv + (size_t)(b*Tt)*QVS + 512 + h*128 + vhalf*64;
    const float* pp = g_proj + (size_t)b * Tt * PSTR;
    float* op = g_o + (size_t)b * Tt * Dd + h*DVv + vhalf*64 + vg*2;

    const float* lsrc[4];
    size_t ladv[4];
    int ldst[4];
    #pragma unroll
    for (int i = 0; i < 4; i++) {
        int f = i * 256 + tid;
        int lq4 = f & 15, ls = (f >> 4) & 3, lr = f >> 6;
        switch (ls) {
            case 0:  lsrc[i] = pp + (size_t)lr*PSTR + 192 + h*64 + lq4*4; ladv[i] = (size_t)CH*PSTR; break;
            case 1:  lsrc[i] = pp + (size_t)lr*PSTR + 64 + lq4*4;         ladv[i] = (size_t)CH*PSTR; break;
            case 2:  lsrc[i] = qp + (size_t)lr*QVS + lq4*4;               ladv[i] = (size_t)CH*QVS;  break;
            default: lsrc[i] = vp + (size_t)lr*QVS + lq4*4;               ladv[i] = (size_t)CH*QVS;  break;
        }
        ldst[i] = (lr*4 + ls)*64 + lq4*4;
    }

    __shared__ __align__(16) float sh[2][CH*256];
    float S0[8], S1[8];
    #pragma unroll
    for (int i = 0; i < 8; i++) { S0[i] = 0.f; S1[i] = 0.f; }

    #pragma unroll
    for (int i = 0; i < 4; i++)
        *(float4*)&sh[0][ldst[i]] = *(const float4*)lsrc[i];
    __syncthreads();

    int buf = 0;
    for (int c = 0; c < Tt/CH; c++) {
        float4 pf[4];
        bool more = (c + 1) < (Tt/CH);
        if (more) {
            #pragma unroll
            for (int i = 0; i < 4; i++)
                pf[i] = *(const float4*)(lsrc[i] + (size_t)(c+1)*ladv[i]);
        }
        const float* cb = sh[buf];
        #pragma unroll 4
        for (int r = 0; r < CH; r++) {
            const float* base = cb + r*256;
            float4 a0 = *(const float4*)(base +       cg*8);
            float4 a1 = *(const float4*)(base +       cg*8 + 4);
            float4 k0 = *(const float4*)(base +  64 + cg*8);
            float4 k1 = *(const float4*)(base +  64 + cg*8 + 4);
            float4 q0 = *(const float4*)(base + 128 + cg*8);
            float4 q1 = *(const float4*)(base + 128 + cg*8 + 4);
            float2 vt = *(const float2*)(base + 192 + vg*2);
            float acc0 = 0.f, acc1 = 0.f;

            S0[0] = fmaf(a0.x, S0[0], k0.x*vt.x); acc0 = fmaf(q0.x, S0[0], acc0);
            S1[0] = fmaf(a0.x, S1[0], k0.x*vt.y); acc1 = fmaf(q0.x, S1[0], acc1);
            S0[1] = fmaf(a0.y, S0[1], k0.y*vt.x); acc0 = fmaf(q0.y, S0[1], acc0);
            S1[1] = fmaf(a0.y, S1[1], k0.y*vt.y); acc1 = fmaf(q0.y, S1[1], acc1);
            S0[2] = fmaf(a0.z, S0[2], k0.z*vt.x); acc0 = fmaf(q0.z, S0[2], acc0);
            S1[2] = fmaf(a0.z, S1[2], k0.z*vt.y); acc1 = fmaf(q0.z, S1[2], acc1);
            S0[3] = fmaf(a0.w, S0[3], k0.w*vt.x); acc0 = fmaf(q0.w, S0[3], acc0);
            S1[3] = fmaf(a0.w, S1[3], k0.w*vt.y); acc1 = fmaf(q0.w, S1[3], acc1);
            S0[4] = fmaf(a1.x, S0[4], k1.x*vt.x); acc0 = fmaf(q1.x, S0[4], acc0);
            S1[4] = fmaf(a1.x, S1[4], k1.x*vt.y); acc1 = fmaf(q1.x, S1[4], acc1);
            S0[5] = fmaf(a1.y, S0[5], k1.y*vt.x); acc0 = fmaf(q1.y, S0[5], acc0);
            S1[5] = fmaf(a1.y, S1[5], k1.y*vt.y); acc1 = fmaf(q1.y, S1[5], acc1);
            S0[6] = fmaf(a1.z, S0[6], k1.z*vt.x); acc0 = fmaf(q1.z, S0[6], acc0);
            S1[6] = fmaf(a1.z, S1[6], k1.z*vt.y); acc1 = fmaf(q1.z, S1[6], acc1);
            S0[7] = fmaf(a1.w, S0[7], k1.w*vt.x); acc0 = fmaf(q1.w, S0[7], acc0);
            S1[7] = fmaf(a1.w, S1[7], k1.w*vt.y); acc1 = fmaf(q1.w, S1[7], acc1);

            acc0 += __shfl_xor_sync(0xffffffffu, acc0, 1);
            acc1 += __shfl_xor_sync(0xffffffffu, acc1, 1);
            acc0 += __shfl_xor_sync(0xffffffffu, acc0, 2);
            acc1 += __shfl_xor_sync(0xffffffffu, acc1, 2);
            acc0 += __shfl_xor_sync(0xffffffffu, acc0, 4);
            acc1 += __shfl_xor_sync(0xffffffffu, acc1, 4);
            if (cg == 0)
                *(float2*)(op + (size_t)(c*CH + r) * Dd) = make_float2(tf32r(acc0), tf32r(acc1));
        }
        if (more) {
            int nb = buf ^ 1;
            #pragma unroll
            for (int i = 0; i < 4; i++)
                *(float4*)&sh[nb][ldst[i]] = pf[i];
            __syncthreads();
            buf = nb;
        }
    }
}

// ---------------- launch ---------------------------------------------------
extern "C" void kernel_launch(void* const* d_in, const int* in_sizes, int n_in,
                              void* d_out, int out_size)
{
    const float* x     = (const float*)d_in[0];
    const float* Wq    = (const float*)d_in[1];
    const float* Wk    = (const float*)d_in[2];
    const float* Wv    = (const float*)d_in[3];
    const float* Qc    = (const float*)d_in[4];
    const float* Vc    = (const float*)d_in[5];
    const float* Wa_w  = (const float*)d_in[6];
    const float* Wa_b  = (const float*)d_in[7];
    const float* Wo    = (const float*)d_in[8];
    const float* gamma = (const float*)d_in[9];
    const float* beta  = (const float*)d_in[10];
    float* out = (float*)d_out;

    float *xn, *wall, *hw, *wo, *proj, *qv, *o;
    cudaGetSymbolAddress((void**)&xn,   g_xn);
    cudaGetSymbolAddress((void**)&wall, g_wall);
    cudaGetSymbolAddress((void**)&hw,   g_hw);
    cudaGetSymbolAddress((void**)&wo,   g_wo);
    cudaGetSymbolAddress((void**)&proj, g_proj);
    cudaGetSymbolAddress((void**)&qv,   g_qv);
    cudaGetSymbolAddress((void**)&o,    g_o);

    int prep_total = WALL_ELEMS + HW_ELEMS + WO_ELEMS;

    // 0: layernorm (tf32-rounded)
    ln_kernel<<<Mm, 256>>>(x, gamma, beta);
    // 1: weight prep (tf32-rounded, incl Wo)
    prep_weights<<<(prep_total + 255)/256, 256>>>(Wq, Wk, Wv, Wa_w, Qc, Vc, Wo);
    // 2: dummy (ncu slot alignment)
    dummy_k<<<1, 32>>>();
    // 3: projection GEMM + fused knorm/sigmoid epilogue
    gemm_tf32<<<dim3(PSTR/128, Mm/128), 128>>>(Dd, Dd, PSTR, 2, xn, wall, proj, nullptr, Wa_b);
    // 4: merged head GEMM: qv = [q_lat|v_lat] @ hw^T, K=64
    gemm_tf32<<<dim3(QVS/128, Mm/128), 128>>>(Cc, PSTR, QVS, 3, proj, hw, qv, nullptr, nullptr);
    // 5: recurrent scan
    scan_kernel<<<128, 256>>>();
    // 6: output GEMM + residual
    gemm_tf32<<<dim3(Dd/128, Mm/128), 128>>>(Dd, Dd, Dd, 1, o, wo, out, x, nullptr);
}